// round 2
// baseline (speedup 1.0000x reference)
#include <cuda_runtime.h>
#include <cstdint>

// ---------------- scratch (no allocations allowed) ----------------
#define BATCH 4
#define CDIM  64
#define NTOK  4096          // H*W
#define KSEL  1024          // NTOK / SPARSE_FACTOR

__device__ float g_q[BATCH * NTOK * CDIM];   // (b, n, c)  -- pre-scaled by C^-0.5
__device__ float g_k[BATCH * CDIM * NTOK];   // (b, c, n)
__device__ float g_v[BATCH * CDIM * NTOK];   // (b, c, n)
__device__ float g_s[BATCH * NTOK * NTOK];   // (b, n, m) scores -> probabilities (256 MB)
__device__ float g_o[BATCH * CDIM * NTOK];   // (b, c, n) attention output pre-projection

// ---------------- kernel 1: fused QKV projection ----------------
// q[b,n,o] = scale * sum_c wq[o,c] x[b,c,n] ; k/v from skip, layout (b,o,n)
__global__ __launch_bounds__(256) void qkv_kernel(const float* __restrict__ x,
                                                  const float* __restrict__ skip,
                                                  const float* __restrict__ w_qkv)
{
    __shared__ float sx[64][64];
    __shared__ float ss[64][64];
    const int b  = blockIdx.y;
    const int n0 = blockIdx.x * 64;
    const int t  = threadIdx.x;

    for (int idx = t; idx < 64 * 64; idx += 256) {
        int c = idx >> 6, j = idx & 63;
        sx[c][j] = x[((b * 64 + c) << 12) + n0 + j];
        ss[c][j] = skip[((b * 64 + c) << 12) + n0 + j];
    }
    __syncthreads();

    const float scale = 0.125f;  // 64^-0.5
    for (int r = 0; r < 48; r++) {
        int outIdx = t + (r << 8);
        int sel = outIdx >> 12;        // 0=q, 1=k, 2=v (uniform per warp)
        int rem = outIdx & 4095;
        int o = rem >> 6, j = rem & 63;
        const float* wrow = w_qkv + ((sel << 6) + o) * 64;
        float acc = 0.f;
        if (sel == 0) {
            #pragma unroll
            for (int c = 0; c < 64; c++) acc += wrow[c] * sx[c][j];
            g_q[(((b << 12) + n0 + j) << 6) + o] = acc * scale;
        } else {
            #pragma unroll
            for (int c = 0; c < 64; c++) acc += wrow[c] * ss[c][j];
            if (sel == 1) g_k[(((b << 6) + o) << 12) + n0 + j] = acc;
            else          g_v[(((b << 6) + o) << 12) + n0 + j] = acc;
        }
    }
}

// ---------------- kernel 2: scores S = Q @ K  (64x64 tile, K-dim = C = 64) ----------------
__global__ __launch_bounds__(256) void scores_kernel()
{
    __shared__ float sQ[64][64];   // [n][c]
    __shared__ float sK[64][64];   // [c][m]
    const int b  = blockIdx.z;
    const int n0 = blockIdx.y * 64;
    const int m0 = blockIdx.x * 64;
    const int t  = threadIdx.x;
    const int tx = t & 15, ty = t >> 4;

    for (int idx = t; idx < 64 * 64; idx += 256) {
        int r = idx >> 6, c = idx & 63;
        sQ[r][c] = g_q[(((b << 12) + n0 + r) << 6) + c];
        sK[r][c] = g_k[(((b << 6) + r) << 12) + m0 + c];
    }
    __syncthreads();

    float acc[4][4];
    #pragma unroll
    for (int i = 0; i < 4; i++)
        #pragma unroll
        for (int j = 0; j < 4; j++) acc[i][j] = 0.f;

    #pragma unroll 8
    for (int c = 0; c < 64; c++) {
        float4 bv = *(const float4*)&sK[c][tx * 4];
        float a0 = sQ[ty * 4 + 0][c];
        float a1 = sQ[ty * 4 + 1][c];
        float a2 = sQ[ty * 4 + 2][c];
        float a3 = sQ[ty * 4 + 3][c];
        acc[0][0] += a0 * bv.x; acc[0][1] += a0 * bv.y; acc[0][2] += a0 * bv.z; acc[0][3] += a0 * bv.w;
        acc[1][0] += a1 * bv.x; acc[1][1] += a1 * bv.y; acc[1][2] += a1 * bv.z; acc[1][3] += a1 * bv.w;
        acc[2][0] += a2 * bv.x; acc[2][1] += a2 * bv.y; acc[2][2] += a2 * bv.z; acc[2][3] += a2 * bv.w;
        acc[3][0] += a3 * bv.x; acc[3][1] += a3 * bv.y; acc[3][2] += a3 * bv.z; acc[3][3] += a3 * bv.w;
    }

    #pragma unroll
    for (int i = 0; i < 4; i++) {
        size_t base = ((size_t)b << 24) + (size_t)(n0 + ty * 4 + i) * NTOK + m0 + tx * 4;
        *(float4*)&g_s[base] = make_float4(acc[i][0], acc[i][1], acc[i][2], acc[i][3]);
    }
}

// ---------------- kernel 3: exact top-k threshold + masked softmax per row ----------------
// masked row v_m = s_m if s_m >= thr else 0 ; softmax over all N entries.
// M = max(s_max, 0); w_m = exp(s_m - M) if kept else exp(-M); p = w / sum(w).
__global__ __launch_bounds__(256) void select_softmax_kernel()
{
    const int row = blockIdx.x;              // b*4096 + n
    const int b = row >> 12, n = row & 4095;
    const size_t base = ((size_t)b << 24) + (size_t)n * NTOK;
    const int t = threadIdx.x;

    __shared__ unsigned su[NTOK];
    __shared__ int hist[256];
    __shared__ unsigned sh_prefix, sh_maxu;
    __shared__ int sh_k;
    __shared__ float sh_z;

    if (t == 0) { sh_maxu = 0u; sh_z = 0.f; }
    __syncthreads();

    float vals[16];
    unsigned my_maxu = 0u;
    #pragma unroll
    for (int i = 0; i < 16; i++) {
        int idx = t + (i << 8);
        float f = g_s[base + idx];
        vals[i] = f;
        unsigned ub = __float_as_uint(f);
        unsigned u = (ub & 0x80000000u) ? ~ub : (ub | 0x80000000u);  // order-preserving
        su[idx] = u;
        my_maxu = my_maxu > u ? my_maxu : u;
    }
    atomicMax(&sh_maxu, my_maxu);
    __syncthreads();

    // 4-pass MSD radix select: find exact bits of the KSEL-th largest value
    unsigned prefix = 0u;
    int kk = KSEL;
    for (int shift = 24; shift >= 0; shift -= 8) {
        hist[t & 255] = 0;                 // 256 threads cover 256 bins
        __syncthreads();
        unsigned um = (shift == 24) ? 0u : (0xFFFFFFFFu << (shift + 8));
        #pragma unroll
        for (int i = 0; i < 16; i++) {
            unsigned u = su[t + (i << 8)];
            if ((u & um) == prefix) atomicAdd(&hist[(u >> shift) & 255], 1);
        }
        __syncthreads();
        if (t == 0) {
            int cum = 0, bin = 255;
            for (; bin > 0; bin--) {
                int c = hist[bin];
                if (cum + c >= kk) break;
                cum += c;
            }
            sh_prefix = prefix | ((unsigned)bin << shift);
            sh_k = kk - cum;
        }
        __syncthreads();
        prefix = sh_prefix;
        kk = sh_k;
    }

    // decode threshold + row max
    unsigned tb = (prefix & 0x80000000u) ? (prefix ^ 0x80000000u) : ~prefix;
    float thr = __uint_as_float(tb);
    unsigned mu = sh_maxu;
    unsigned mb = (mu & 0x80000000u) ? (mu ^ 0x80000000u) : ~mu;
    float smax = __uint_as_float(mb);
    float M = fmaxf(smax, 0.f);
    float expM = __expf(-M);

    float w[16];
    float zloc = 0.f;
    #pragma unroll
    for (int i = 0; i < 16; i++) {
        float wv = (vals[i] >= thr) ? __expf(vals[i] - M) : expM;
        w[i] = wv;
        zloc += wv;
    }
    #pragma unroll
    for (int off = 16; off; off >>= 1) zloc += __shfl_xor_sync(0xffffffffu, zloc, off);
    if ((t & 31) == 0) atomicAdd(&sh_z, zloc);
    __syncthreads();

    float invZ = 1.f / sh_z;
    #pragma unroll
    for (int i = 0; i < 16; i++) g_s[base + t + (i << 8)] = w[i] * invZ;
}

// ---------------- kernel 4: O = V @ P^T  (o[b,c,n] = sum_m v[b,c,m] p[b,n,m]) ----------------
__global__ __launch_bounds__(256) void av_kernel()
{
    __shared__ float sV[64][65];   // [c][m]  (pad avoids same-bank strides)
    __shared__ float sP[64][65];   // [n][m]
    const int b  = blockIdx.y;
    const int n0 = blockIdx.x * 64;
    const int t  = threadIdx.x;
    const int tx = t & 15, ty = t >> 4;   // tx->n, ty->c

    float acc[4][4];
    #pragma unroll
    for (int i = 0; i < 4; i++)
        #pragma unroll
        for (int j = 0; j < 4; j++) acc[i][j] = 0.f;

    for (int m0 = 0; m0 < NTOK; m0 += 64) {
        __syncthreads();
        for (int idx = t; idx < 64 * 64; idx += 256) {
            int r = idx >> 6, q = idx & 63;
            sV[r][q] = g_v[(((b << 6) + r) << 12) + m0 + q];
            sP[r][q] = g_s[((size_t)b << 24) + (size_t)(n0 + r) * NTOK + m0 + q];
        }
        __syncthreads();

        #pragma unroll 8
        for (int m = 0; m < 64; m++) {
            float a0 = sV[ty * 4 + 0][m];
            float a1 = sV[ty * 4 + 1][m];
            float a2 = sV[ty * 4 + 2][m];
            float a3 = sV[ty * 4 + 3][m];
            float p0 = sP[tx * 4 + 0][m];
            float p1 = sP[tx * 4 + 1][m];
            float p2 = sP[tx * 4 + 2][m];
            float p3 = sP[tx * 4 + 3][m];
            acc[0][0] += a0 * p0; acc[0][1] += a0 * p1; acc[0][2] += a0 * p2; acc[0][3] += a0 * p3;
            acc[1][0] += a1 * p0; acc[1][1] += a1 * p1; acc[1][2] += a1 * p2; acc[1][3] += a1 * p3;
            acc[2][0] += a2 * p0; acc[2][1] += a2 * p1; acc[2][2] += a2 * p2; acc[2][3] += a2 * p3;
            acc[3][0] += a3 * p0; acc[3][1] += a3 * p1; acc[3][2] += a3 * p2; acc[3][3] += a3 * p3;
        }
    }

    #pragma unroll
    for (int i = 0; i < 4; i++) {
        int c = ty * 4 + i;
        size_t base = (size_t)(((b << 6) + c) << 12) + n0 + tx * 4;
        *(float4*)&g_o[base] = make_float4(acc[i][0], acc[i][1], acc[i][2], acc[i][3]);
    }
}

// ---------------- kernel 5: output projection + bias + residual ----------------
__global__ __launch_bounds__(256) void proj_kernel(const float* __restrict__ x,
                                                   const float* __restrict__ w_out,
                                                   const float* __restrict__ b_out,
                                                   const float* __restrict__ gamma,
                                                   float* __restrict__ out)
{
    __shared__ float sT[64][64];
    const int b  = blockIdx.y;
    const int n0 = blockIdx.x * 64;
    const int t  = threadIdx.x;

    for (int idx = t; idx < 64 * 64; idx += 256) {
        int c = idx >> 6, j = idx & 63;
        sT[c][j] = g_o[(((b << 6) + c) << 12) + n0 + j];
    }
    __syncthreads();

    const float g = gamma[0];
    for (int r = 0; r < 16; r++) {
        int outIdx = t + (r << 8);
        int o = outIdx >> 6, j = outIdx & 63;
        const float* wrow = w_out + o * 64;
        float acc = b_out[o];
        #pragma unroll
        for (int c = 0; c < 64; c++) acc += wrow[c] * sT[c][j];
        size_t gi = (size_t)(((b << 6) + o) << 12) + n0 + j;
        out[gi] = g * acc + x[gi];
    }
}

// ---------------- launch ----------------
extern "C" void kernel_launch(void* const* d_in, const int* in_sizes, int n_in,
                              void* d_out, int out_size)
{
    const float* x     = (const float*)d_in[0];
    const float* skip  = (const float*)d_in[1];
    const float* w_qkv = (const float*)d_in[2];
    const float* w_out = (const float*)d_in[3];
    const float* b_out = (const float*)d_in[4];
    const float* gamma = (const float*)d_in[5];
    float* out = (float*)d_out;

    qkv_kernel<<<dim3(64, BATCH), 256>>>(x, skip, w_qkv);
    scores_kernel<<<dim3(64, 64, BATCH), 256>>>();
    select_softmax_kernel<<<BATCH * NTOK, 256>>>();
    av_kernel<<<dim3(64, BATCH), 256>>>();
    proj_kernel<<<dim3(64, BATCH), 256>>>(x, w_out, b_out, gamma, out);
}

// round 3
// speedup vs baseline: 1.2268x; 1.2268x over previous
#include <cuda_runtime.h>
#include <cstdint>

#define BATCH 4
#define CDIM  64
#define NTOK  4096
#define KSEL  1024

typedef unsigned long long u64;

__device__ float g_q[BATCH * NTOK * CDIM];   // (b, n, c)  pre-scaled by C^-0.5
__device__ float g_k[BATCH * CDIM * NTOK];   // (b, c, m)
__device__ float g_v[BATCH * NTOK * CDIM];   // (b, m, c)  TRANSPOSED for av
__device__ float g_s[BATCH * NTOK * NTOK];   // (b, n, m) scores -> probabilities
__device__ float g_o[BATCH * CDIM * NTOK];   // (b, c, n)

union F4P { float4 f; u64 p[2]; };

__device__ __forceinline__ u64 pk(float x, float y) {
    u64 r; asm("mov.b64 %0, {%1, %2};" : "=l"(r) : "f"(x), "f"(y)); return r;
}
__device__ __forceinline__ void fma2(u64& d, u64 a, u64 b) {
    asm("fma.rn.f32x2 %0, %1, %2, %0;" : "+l"(d) : "l"(a), "l"(b));
}
__device__ __forceinline__ void unpk(u64 v, float& lo, float& hi) {
    asm("mov.b64 {%0, %1}, %2;" : "=f"(lo), "=f"(hi) : "l"(v));
}

// ---------------- kernel 0: zero g_o (split-K accumulator) ----------------
__global__ __launch_bounds__(256) void zero_o_kernel()
{
    int i = blockIdx.x * 256 + threadIdx.x;
    ((float4*)g_o)[i] = make_float4(0.f, 0.f, 0.f, 0.f);
}

// ---------------- kernel 1: fused QKV projection ----------------
__global__ __launch_bounds__(256) void qkv_kernel(const float* __restrict__ x,
                                                  const float* __restrict__ skip,
                                                  const float* __restrict__ w_qkv)
{
    __shared__ float sx[64][64];
    __shared__ float ss[64][64];
    const int b  = blockIdx.y;
    const int n0 = blockIdx.x * 64;
    const int t  = threadIdx.x;

    for (int idx = t; idx < 64 * 64; idx += 256) {
        int c = idx >> 6, j = idx & 63;
        sx[c][j] = x[((b * 64 + c) << 12) + n0 + j];
        ss[c][j] = skip[((b * 64 + c) << 12) + n0 + j];
    }
    __syncthreads();

    const float scale = 0.125f;
    for (int r = 0; r < 48; r++) {
        int outIdx = t + (r << 8);
        int sel = outIdx >> 12;           // 0=q, 1=k, 2=v
        int rem = outIdx & 4095;
        int o = rem >> 6, j = rem & 63;
        const float* wrow = w_qkv + ((sel << 6) + o) * 64;
        float acc = 0.f;
        if (sel == 0) {
            #pragma unroll
            for (int c = 0; c < 64; c++) acc += wrow[c] * sx[c][j];
            g_q[(((b << 12) + n0 + j) << 6) + o] = acc * scale;
        } else {
            #pragma unroll
            for (int c = 0; c < 64; c++) acc += wrow[c] * ss[c][j];
            if (sel == 1) g_k[(((b << 6) + o) << 12) + n0 + j] = acc;
            else          g_v[(((b << 12) + n0 + j) << 6) + o] = acc;   // (b,m,c)
        }
    }
}

// ---------------- kernel 2: S = Q @ K, 64n x 128m tile, f32x2 FMA ----------------
__global__ __launch_bounds__(256) void scores_kernel()
{
    __shared__ float sQ[64][64];     // [n][c] 16KB
    __shared__ float sK[64][128];    // [c][m] 32KB
    const int b  = blockIdx.z;
    const int n0 = blockIdx.y * 64;
    const int m0 = blockIdx.x * 128;
    const int t  = threadIdx.x;
    const int tx = t & 15, ty = t >> 4;   // tx -> m (8 each), ty -> n (4 each)

    #pragma unroll
    for (int k = 0; k < 4; k++) {
        int idx = t + k * 256;            // 1024 float4 total
        int r = idx >> 4, c4 = idx & 15;
        *(float4*)&sQ[r][c4 * 4] = *(const float4*)&g_q[(((b << 12) + n0 + r) << 6) + c4 * 4];
    }
    #pragma unroll
    for (int k = 0; k < 8; k++) {
        int idx = t + k * 256;            // 2048 float4 total
        int r = idx >> 5, c4 = idx & 31;
        *(float4*)&sK[r][c4 * 4] = *(const float4*)&g_k[(((b << 6) + r) << 12) + m0 + c4 * 4];
    }
    __syncthreads();

    u64 acc[4][4];
    #pragma unroll
    for (int i = 0; i < 4; i++)
        #pragma unroll
        for (int j = 0; j < 4; j++) acc[i][j] = 0ull;

    #pragma unroll 8
    for (int c = 0; c < 64; c++) {
        F4P b0, b1;
        b0.f = *(float4*)&sK[c][tx * 8];
        b1.f = *(float4*)&sK[c][tx * 8 + 4];
        #pragma unroll
        for (int i = 0; i < 4; i++) {
            float a = sQ[ty * 4 + i][c];
            u64 ap = pk(a, a);
            fma2(acc[i][0], ap, b0.p[0]);
            fma2(acc[i][1], ap, b0.p[1]);
            fma2(acc[i][2], ap, b1.p[0]);
            fma2(acc[i][3], ap, b1.p[1]);
        }
    }

    #pragma unroll
    for (int i = 0; i < 4; i++) {
        size_t base = ((size_t)b << 24) + (size_t)(n0 + ty * 4 + i) * NTOK + m0 + tx * 8;
        F4P o0, o1;
        o0.p[0] = acc[i][0]; o0.p[1] = acc[i][1];
        o1.p[0] = acc[i][2]; o1.p[1] = acc[i][3];
        *(float4*)&g_s[base]     = o0.f;
        *(float4*)&g_s[base + 4] = o1.f;
    }
}

// ---------------- kernel 3: exact top-k threshold + masked softmax ----------------
__global__ __launch_bounds__(256) void select_softmax_kernel()
{
    const int row = blockIdx.x;
    const int b = row >> 12, n = row & 4095;
    const size_t base = ((size_t)b << 24) + (size_t)n * NTOK;
    const int t = threadIdx.x;
    const int wid = t >> 5;

    __shared__ int hist[8][256];
    __shared__ int sscan[256];
    __shared__ unsigned sh_prefix, sh_maxu;
    __shared__ int sh_k;
    __shared__ float sh_z;

    if (t == 0) { sh_maxu = 0u; sh_z = 0.f; }

    // Load 16 contiguous values per thread via 4x LDG.128
    float vals[16];
    unsigned uv[16];
    const size_t myb = base + (size_t)t * 16;
    #pragma unroll
    for (int k = 0; k < 4; k++) {
        float4 f = *(const float4*)&g_s[myb + k * 4];
        vals[k * 4 + 0] = f.x; vals[k * 4 + 1] = f.y;
        vals[k * 4 + 2] = f.z; vals[k * 4 + 3] = f.w;
    }
    unsigned my_maxu = 0u;
    #pragma unroll
    for (int i = 0; i < 16; i++) {
        unsigned ub = __float_as_uint(vals[i]);
        unsigned u = (ub & 0x80000000u) ? ~ub : (ub | 0x80000000u);
        uv[i] = u;
        my_maxu = my_maxu > u ? my_maxu : u;
    }
    #pragma unroll
    for (int off = 16; off; off >>= 1) {
        unsigned o = __shfl_xor_sync(0xffffffffu, my_maxu, off);
        my_maxu = my_maxu > o ? my_maxu : o;
    }
    if ((t & 31) == 0) atomicMax(&sh_maxu, my_maxu);
    __syncthreads();

    // 4-pass MSD radix select, values in registers, per-warp histograms
    unsigned prefix = 0u;
    int kk = KSEL;
    for (int shift = 24; shift >= 0; shift -= 8) {
        #pragma unroll
        for (int w = 0; w < 8; w++) hist[w][t] = 0;
        __syncthreads();

        unsigned um = (shift == 24) ? 0u : (0xFFFFFFFFu << (shift + 8));
        int* myh = hist[wid];
        #pragma unroll
        for (int i = 0; i < 16; i++) {
            unsigned u = uv[i];
            if ((u & um) == prefix) atomicAdd(&myh[(u >> shift) & 255], 1);
        }
        __syncthreads();

        int tot = 0;
        #pragma unroll
        for (int w = 0; w < 8; w++) tot += hist[w][t];
        int v = tot;
        sscan[t] = v;
        __syncthreads();
        // inclusive suffix scan: sscan[t] = sum of tot over bins >= t
        #pragma unroll
        for (int off = 1; off < 256; off <<= 1) {
            int add = (t + off < 256) ? sscan[t + off] : 0;
            __syncthreads();
            v += add;
            sscan[t] = v;
            __syncthreads();
        }
        int cum_incl = v;
        int cum_excl = v - tot;
        if (cum_excl < kk && kk <= cum_incl) {
            sh_prefix = prefix | ((unsigned)t << shift);
            sh_k = kk - cum_excl;
        }
        __syncthreads();
        prefix = sh_prefix;
        kk = sh_k;
    }

    unsigned tb = (prefix & 0x80000000u) ? (prefix ^ 0x80000000u) : ~prefix;
    float thr = __uint_as_float(tb);
    unsigned mu = sh_maxu;
    unsigned mb = (mu & 0x80000000u) ? (mu ^ 0x80000000u) : ~mu;
    float smax = __uint_as_float(mb);
    float M = fmaxf(smax, 0.f);
    float expM = __expf(-M);

    float w[16];
    float zloc = 0.f;
    #pragma unroll
    for (int i = 0; i < 16; i++) {
        float wv = (vals[i] >= thr) ? __expf(vals[i] - M) : expM;
        w[i] = wv;
        zloc += wv;
    }
    #pragma unroll
    for (int off = 16; off; off >>= 1) zloc += __shfl_xor_sync(0xffffffffu, zloc, off);
    if ((t & 31) == 0) atomicAdd(&sh_z, zloc);
    __syncthreads();

    float invZ = 1.f / sh_z;
    #pragma unroll
    for (int k = 0; k < 4; k++) {
        float4 f = make_float4(w[k*4+0] * invZ, w[k*4+1] * invZ,
                               w[k*4+2] * invZ, w[k*4+3] * invZ);
        *(float4*)&g_s[myb + k * 4] = f;
    }
}

// ---------------- kernel 4: out^T(n,c) = P(n,m) x Vt(m,c), split-K, f32x2 ----------------
__global__ __launch_bounds__(256) void av_kernel()
{
    __shared__ u64  sPd[128][17];    // packed-dup P [n][m-sub], padded
    __shared__ float sV[16][64];     // [m-sub][c]
    const int b     = blockIdx.z;
    const int chunk = blockIdx.y;    // 8 chunks of 512 m
    const int n0    = blockIdx.x * 128;
    const int t  = threadIdx.x;
    const int tx = t & 15, ty = t >> 4;    // tx -> c (4 each), ty -> n (8 each)
    const size_t bbase = ((size_t)b << 24);

    u64 acc[8][2];
    #pragma unroll
    for (int i = 0; i < 8; i++) { acc[i][0] = 0ull; acc[i][1] = 0ull; }

    for (int mt = 0; mt < 32; mt++) {
        int mbase = chunk * 512 + mt * 16;
        #pragma unroll
        for (int k = 0; k < 2; k++) {
            int idx = t + k * 256;           // 512 float4 total
            int r = idx >> 2, m4 = idx & 3;
            float4 pv = *(const float4*)&g_s[bbase + (size_t)(n0 + r) * NTOK + mbase + m4 * 4];
            sPd[r][m4 * 4 + 0] = pk(pv.x, pv.x);
            sPd[r][m4 * 4 + 1] = pk(pv.y, pv.y);
            sPd[r][m4 * 4 + 2] = pk(pv.z, pv.z);
            sPd[r][m4 * 4 + 3] = pk(pv.w, pv.w);
        }
        {
            int r = t >> 4, c4 = t & 15;     // 256 float4 total
            *(float4*)&sV[r][c4 * 4] = *(const float4*)&g_v[(((b << 12) + mbase + r) << 6) + c4 * 4];
        }
        __syncthreads();

        #pragma unroll 16
        for (int m = 0; m < 16; m++) {
            F4P bv;
            bv.f = *(float4*)&sV[m][tx * 4];
            #pragma unroll
            for (int i = 0; i < 8; i++) {
                u64 ap = sPd[ty * 8 + i][m];
                fma2(acc[i][0], ap, bv.p[0]);
                fma2(acc[i][1], ap, bv.p[1]);
            }
        }
        __syncthreads();
    }

    #pragma unroll
    for (int i = 0; i < 8; i++) {
        int nn = n0 + ty * 8 + i;
        #pragma unroll
        for (int j = 0; j < 2; j++) {
            float lo, hi;
            unpk(acc[i][j], lo, hi);
            int c0 = tx * 4 + j * 2;
            atomicAdd(&g_o[(size_t)(((b << 6) + c0) << 12) + nn], lo);
            atomicAdd(&g_o[(size_t)(((b << 6) + c0 + 1) << 12) + nn], hi);
        }
    }
}

// ---------------- kernel 5: output projection + bias + residual ----------------
__global__ __launch_bounds__(256) void proj_kernel(const float* __restrict__ x,
                                                   const float* __restrict__ w_out,
                                                   const float* __restrict__ b_out,
                                                   const float* __restrict__ gamma,
                                                   float* __restrict__ out)
{
    __shared__ float sT[64][64];
    const int b  = blockIdx.y;
    const int n0 = blockIdx.x * 64;
    const int t  = threadIdx.x;

    for (int idx = t; idx < 64 * 64; idx += 256) {
        int c = idx >> 6, j = idx & 63;
        sT[c][j] = g_o[(((b << 6) + c) << 12) + n0 + j];
    }
    __syncthreads();

    const float g = gamma[0];
    for (int r = 0; r < 16; r++) {
        int outIdx = t + (r << 8);
        int o = outIdx >> 6, j = outIdx & 63;
        const float* wrow = w_out + o * 64;
        float acc = b_out[o];
        #pragma unroll
        for (int c = 0; c < 64; c++) acc += wrow[c] * sT[c][j];
        size_t gi = (size_t)(((b << 6) + o) << 12) + n0 + j;
        out[gi] = g * acc + x[gi];
    }
}

// ---------------- launch ----------------
extern "C" void kernel_launch(void* const* d_in, const int* in_sizes, int n_in,
                              void* d_out, int out_size)
{
    const float* x     = (const float*)d_in[0];
    const float* skip  = (const float*)d_in[1];
    const float* w_qkv = (const float*)d_in[2];
    const float* w_out = (const float*)d_in[3];
    const float* b_out = (const float*)d_in[4];
    const float* gamma = (const float*)d_in[5];
    float* out = (float*)d_out;

    zero_o_kernel<<<1024, 256>>>();
    qkv_kernel<<<dim3(64, BATCH), 256>>>(x, skip, w_qkv);
    scores_kernel<<<dim3(32, 64, BATCH), 256>>>();
    select_softmax_kernel<<<BATCH * NTOK, 256>>>();
    av_kernel<<<dim3(32, 8, BATCH), 256>>>();
    proj_kernel<<<dim3(64, BATCH), 256>>>(x, w_out, b_out, gamma, out);
}

// round 4
// speedup vs baseline: 1.2927x; 1.0537x over previous
#include <cuda_runtime.h>
#include <cuda_bf16.h>
#include <cstdint>

#define BATCH 4
#define CDIM  64
#define NTOK  4096
#define KSEL  1024

typedef unsigned long long u64;

__device__ float g_q[BATCH * NTOK * CDIM];          // (b, n, c)  pre-scaled
__device__ float g_k[BATCH * CDIM * NTOK];          // (b, c, m)
__device__ float g_v[BATCH * NTOK * CDIM];          // (b, m, c)
__device__ float g_s[BATCH * NTOK * NTOK];          // (b, n, m) fp32 scores
__device__ __nv_bfloat16 g_p[BATCH * NTOK * NTOK];  // (b, n, m) bf16 probabilities
__device__ float g_o[BATCH * CDIM * NTOK];          // (b, c, n)

union F4P { float4 f; u64 p[2]; };

__device__ __forceinline__ u64 pk(float x, float y) {
    u64 r; asm("mov.b64 %0, {%1, %2};" : "=l"(r) : "f"(x), "f"(y)); return r;
}
__device__ __forceinline__ void fma2(u64& d, u64 a, u64 b) {
    asm("fma.rn.f32x2 %0, %1, %2, %0;" : "+l"(d) : "l"(a), "l"(b));
}
__device__ __forceinline__ void unpk(u64 v, float& lo, float& hi) {
    asm("mov.b64 {%0, %1}, %2;" : "=f"(lo), "=f"(hi) : "l"(v));
}
// pack: result = {hi_half = hi, lo_half = lo}
__device__ __forceinline__ unsigned pack_bf16x2(float hi, float lo) {
    unsigned r;
    asm("cvt.rn.bf16x2.f32 %0, %1, %2;" : "=r"(r) : "f"(hi), "f"(lo));
    return r;
}

// ---------------- kernel 0: zero g_o ----------------
__global__ __launch_bounds__(256) void zero_o_kernel()
{
    int i = blockIdx.x * 256 + threadIdx.x;
    ((float4*)g_o)[i] = make_float4(0.f, 0.f, 0.f, 0.f);
}

// ---------------- kernel 1: fused QKV projection ----------------
__global__ __launch_bounds__(256) void qkv_kernel(const float* __restrict__ x,
                                                  const float* __restrict__ skip,
                                                  const float* __restrict__ w_qkv)
{
    __shared__ float sx[64][64];
    __shared__ float ss[64][64];
    const int b  = blockIdx.y;
    const int n0 = blockIdx.x * 64;
    const int t  = threadIdx.x;

    for (int idx = t; idx < 64 * 64; idx += 256) {
        int c = idx >> 6, j = idx & 63;
        sx[c][j] = x[((b * 64 + c) << 12) + n0 + j];
        ss[c][j] = skip[((b * 64 + c) << 12) + n0 + j];
    }
    __syncthreads();

    const float scale = 0.125f;
    for (int r = 0; r < 48; r++) {
        int outIdx = t + (r << 8);
        int sel = outIdx >> 12;
        int rem = outIdx & 4095;
        int o = rem >> 6, j = rem & 63;
        const float* wrow = w_qkv + ((sel << 6) + o) * 64;
        float acc = 0.f;
        if (sel == 0) {
            #pragma unroll
            for (int c = 0; c < 64; c++) acc += wrow[c] * sx[c][j];
            g_q[(((b << 12) + n0 + j) << 6) + o] = acc * scale;
        } else {
            #pragma unroll
            for (int c = 0; c < 64; c++) acc += wrow[c] * ss[c][j];
            if (sel == 1) g_k[(((b << 6) + o) << 12) + n0 + j] = acc;
            else          g_v[(((b << 12) + n0 + j) << 6) + o] = acc;
        }
    }
}

// ---------------- kernel 2: S = Q @ K, 64n x 128m tile, f32x2 ----------------
__global__ __launch_bounds__(256) void scores_kernel()
{
    __shared__ float sQ[64][64];
    __shared__ float sK[64][128];
    const int b  = blockIdx.z;
    const int n0 = blockIdx.y * 64;
    const int m0 = blockIdx.x * 128;
    const int t  = threadIdx.x;
    const int tx = t & 15, ty = t >> 4;

    #pragma unroll
    for (int k = 0; k < 4; k++) {
        int idx = t + k * 256;
        int r = idx >> 4, c4 = idx & 15;
        *(float4*)&sQ[r][c4 * 4] = *(const float4*)&g_q[(((b << 12) + n0 + r) << 6) + c4 * 4];
    }
    #pragma unroll
    for (int k = 0; k < 8; k++) {
        int idx = t + k * 256;
        int r = idx >> 5, c4 = idx & 31;
        *(float4*)&sK[r][c4 * 4] = *(const float4*)&g_k[(((b << 6) + r) << 12) + m0 + c4 * 4];
    }
    __syncthreads();

    u64 acc[4][4];
    #pragma unroll
    for (int i = 0; i < 4; i++)
        #pragma unroll
        for (int j = 0; j < 4; j++) acc[i][j] = 0ull;

    #pragma unroll 8
    for (int c = 0; c < 64; c++) {
        F4P b0, b1;
        b0.f = *(float4*)&sK[c][tx * 8];
        b1.f = *(float4*)&sK[c][tx * 8 + 4];
        #pragma unroll
        for (int i = 0; i < 4; i++) {
            float a = sQ[ty * 4 + i][c];
            u64 ap = pk(a, a);
            fma2(acc[i][0], ap, b0.p[0]);
            fma2(acc[i][1], ap, b0.p[1]);
            fma2(acc[i][2], ap, b1.p[0]);
            fma2(acc[i][3], ap, b1.p[1]);
        }
    }

    #pragma unroll
    for (int i = 0; i < 4; i++) {
        size_t base = ((size_t)b << 24) + (size_t)(n0 + ty * 4 + i) * NTOK + m0 + tx * 8;
        F4P o0, o1;
        o0.p[0] = acc[i][0]; o0.p[1] = acc[i][1];
        o1.p[0] = acc[i][2]; o1.p[1] = acc[i][3];
        *(float4*)&g_s[base]     = o0.f;
        *(float4*)&g_s[base + 4] = o1.f;
    }
}

// ---------------- kernel 3: exact top-k threshold + masked softmax -> bf16 probs ----------------
__global__ __launch_bounds__(256) void select_softmax_kernel()
{
    const int row = blockIdx.x;
    const int b = row >> 12, n = row & 4095;
    const size_t base = ((size_t)b << 24) + (size_t)n * NTOK;
    const int t = threadIdx.x;
    const int wid = t >> 5, lane = t & 31;

    __shared__ int hist8[8][256];
    __shared__ unsigned candA[4096];
    __shared__ unsigned candB[4096];
    __shared__ int warpTot[8];
    __shared__ int sh_cnt[4];
    __shared__ unsigned sh_bin;
    __shared__ int sh_kk;
    __shared__ unsigned sh_maxu;
    __shared__ float sh_z;

    if (t == 0) { sh_maxu = 0u; sh_z = 0.f; }
    if (t < 4) sh_cnt[t] = 0;
    __syncthreads();

    // load 16 contiguous values per thread
    float vals[16];
    unsigned uv[16];
    const size_t myb = base + (size_t)t * 16;
    #pragma unroll
    for (int k = 0; k < 4; k++) {
        float4 f = *(const float4*)&g_s[myb + k * 4];
        vals[k * 4 + 0] = f.x; vals[k * 4 + 1] = f.y;
        vals[k * 4 + 2] = f.z; vals[k * 4 + 3] = f.w;
    }
    unsigned my_maxu = 0u;
    #pragma unroll
    for (int i = 0; i < 16; i++) {
        unsigned ub = __float_as_uint(vals[i]);
        unsigned u = (ub & 0x80000000u) ? ~ub : (ub | 0x80000000u);
        uv[i] = u;
        my_maxu = my_maxu > u ? my_maxu : u;
    }
    #pragma unroll
    for (int off = 16; off; off >>= 1) {
        unsigned o = __shfl_xor_sync(0xffffffffu, my_maxu, off);
        my_maxu = my_maxu > o ? my_maxu : o;
    }
    if (lane == 0) atomicMax(&sh_maxu, my_maxu);

    // ---- pass 1 (bits 31:24), per-warp histograms, values in regs ----
    #pragma unroll
    for (int w = 0; w < 8; w++) hist8[w][t] = 0;
    __syncthreads();
    int* myh = hist8[wid];
    #pragma unroll
    for (int i = 0; i < 16; i++) atomicAdd(&myh[uv[i] >> 24], 1);
    __syncthreads();

    int tot = 0;
    #pragma unroll
    for (int w = 0; w < 8; w++) tot += hist8[w][t];
    // warp-level inclusive suffix scan over bins (bin index = t)
    int v = tot;
    #pragma unroll
    for (int off = 1; off < 32; off <<= 1) {
        int o = __shfl_down_sync(0xffffffffu, v, off);
        if (lane + off < 32) v += o;
    }
    if (lane == 0) warpTot[wid] = v;
    __syncthreads();
    int above = 0;
    #pragma unroll
    for (int w = 0; w < 8; w++) if (w > wid) above += warpTot[w];
    int cum_incl = v + above;
    int cum_excl = cum_incl - tot;
    if (cum_excl < KSEL && KSEL <= cum_incl) { sh_bin = (unsigned)t; sh_kk = KSEL - cum_excl; }
    __syncthreads();
    unsigned bin = sh_bin;
    int kk = sh_kk;
    unsigned prefix = bin << 24;

    // compact candidates (top byte == bin) from registers into shared
    {
        int cnt = 0;
        #pragma unroll
        for (int i = 0; i < 16; i++) cnt += ((uv[i] >> 24) == bin);
        int pos = 0;
        if (cnt) pos = atomicAdd(&sh_cnt[0], cnt);
        #pragma unroll
        for (int i = 0; i < 16; i++)
            if ((uv[i] >> 24) == bin) candA[pos++] = uv[i];
    }
    __syncthreads();
    int ncand = sh_cnt[0];
    unsigned* cur = candA;
    unsigned* nxt = candB;
    int stage = 1;

    // ---- passes 2-4 over the candidate list only ----
    for (int shift = 16; shift >= 0; shift -= 8) {
        hist8[0][t] = 0;
        __syncthreads();
        for (int i = t; i < ncand; i += 256)
            atomicAdd(&hist8[0][(cur[i] >> shift) & 255], 1);
        __syncthreads();

        tot = hist8[0][t];
        v = tot;
        #pragma unroll
        for (int off = 1; off < 32; off <<= 1) {
            int o = __shfl_down_sync(0xffffffffu, v, off);
            if (lane + off < 32) v += o;
        }
        if (lane == 0) warpTot[wid] = v;
        __syncthreads();
        above = 0;
        #pragma unroll
        for (int w = 0; w < 8; w++) if (w > wid) above += warpTot[w];
        cum_incl = v + above;
        cum_excl = cum_incl - tot;
        if (cum_excl < kk && kk <= cum_incl) { sh_bin = (unsigned)t; sh_kk = kk - cum_excl; }
        __syncthreads();
        bin = sh_bin;
        kk = sh_kk;
        prefix |= bin << shift;

        if (shift > 0) {
            for (int i = t; i < ncand; i += 256) {
                unsigned u = cur[i];
                if (((u >> shift) & 255) == bin) {
                    int p = atomicAdd(&sh_cnt[stage], 1);
                    nxt[p] = u;
                }
            }
            __syncthreads();
            ncand = sh_cnt[stage];
            stage++;
            unsigned* tmp = cur; cur = nxt; nxt = tmp;
            __syncthreads();
        }
    }

    // decode threshold + max, softmax
    unsigned tb = (prefix & 0x80000000u) ? (prefix ^ 0x80000000u) : ~prefix;
    float thr = __uint_as_float(tb);
    unsigned mu = sh_maxu;
    unsigned mb = (mu & 0x80000000u) ? (mu ^ 0x80000000u) : ~mu;
    float smax = __uint_as_float(mb);
    float M = fmaxf(smax, 0.f);
    float expM = __expf(-M);

    float w[16];
    float zloc = 0.f;
    #pragma unroll
    for (int i = 0; i < 16; i++) {
        float wv = (vals[i] >= thr) ? __expf(vals[i] - M) : expM;
        w[i] = wv;
        zloc += wv;
    }
    #pragma unroll
    for (int off = 16; off; off >>= 1) zloc += __shfl_xor_sync(0xffffffffu, zloc, off);
    if (lane == 0) atomicAdd(&sh_z, zloc);
    __syncthreads();

    float invZ = 1.f / sh_z;
    // write 16 probs as bf16: 2x 16B stores
    #pragma unroll
    for (int h = 0; h < 2; h++) {
        uint4 o;
        o.x = pack_bf16x2(w[h*8+1] * invZ, w[h*8+0] * invZ);
        o.y = pack_bf16x2(w[h*8+3] * invZ, w[h*8+2] * invZ);
        o.z = pack_bf16x2(w[h*8+5] * invZ, w[h*8+4] * invZ);
        o.w = pack_bf16x2(w[h*8+7] * invZ, w[h*8+6] * invZ);
        *(uint4*)&g_p[myb + h * 8] = o;
    }
}

// ---------------- kernel 4: O(n,c) = P(n,m) x Vt(m,c), split-K, f32x2, bf16 P ----------------
__global__ __launch_bounds__(256) void av_kernel()
{
    __shared__ u64  sPd[128][17];
    __shared__ float sV[16][64];
    const int b     = blockIdx.z;
    const int chunk = blockIdx.y;
    const int n0    = blockIdx.x * 128;
    const int t  = threadIdx.x;
    const int tx = t & 15, ty = t >> 4;
    const size_t bbase = ((size_t)b << 24);

    u64 acc[8][2];
    #pragma unroll
    for (int i = 0; i < 8; i++) { acc[i][0] = 0ull; acc[i][1] = 0ull; }

    for (int mt = 0; mt < 32; mt++) {
        int mbase = chunk * 512 + mt * 16;
        {
            // 128 rows x 16 m bf16 -> 256 x uint4 (8 bf16 each); 1 per thread
            int r = t >> 1, h = t & 1;
            uint4 raw = *(const uint4*)&g_p[bbase + (size_t)(n0 + r) * NTOK + mbase + h * 8];
            unsigned uw[4] = {raw.x, raw.y, raw.z, raw.w};
            #pragma unroll
            for (int j = 0; j < 4; j++) {
                float flo = __uint_as_float(uw[j] << 16);
                float fhi = __uint_as_float(uw[j] & 0xffff0000u);
                sPd[r][h * 8 + j * 2 + 0] = pk(flo, flo);
                sPd[r][h * 8 + j * 2 + 1] = pk(fhi, fhi);
            }
        }
        {
            int r = t >> 4, c4 = t & 15;
            *(float4*)&sV[r][c4 * 4] = *(const float4*)&g_v[(((b << 12) + mbase + r) << 6) + c4 * 4];
        }
        __syncthreads();

        #pragma unroll 16
        for (int m = 0; m < 16; m++) {
            F4P bv;
            bv.f = *(float4*)&sV[m][tx * 4];
            #pragma unroll
            for (int i = 0; i < 8; i++) {
                u64 ap = sPd[ty * 8 + i][m];
                fma2(acc[i][0], ap, bv.p[0]);
                fma2(acc[i][1], ap, bv.p[1]);
            }
        }
        __syncthreads();
    }

    #pragma unroll
    for (int i = 0; i < 8; i++) {
        int nn = n0 + ty * 8 + i;
        #pragma unroll
        for (int j = 0; j < 2; j++) {
            float lo, hi;
            unpk(acc[i][j], lo, hi);
            int c0 = tx * 4 + j * 2;
            atomicAdd(&g_o[(size_t)(((b << 6) + c0) << 12) + nn], lo);
            atomicAdd(&g_o[(size_t)(((b << 6) + c0 + 1) << 12) + nn], hi);
        }
    }
}

// ---------------- kernel 5: output projection + bias + residual ----------------
__global__ __launch_bounds__(256) void proj_kernel(const float* __restrict__ x,
                                                   const float* __restrict__ w_out,
                                                   const float* __restrict__ b_out,
                                                   const float* __restrict__ gamma,
                                                   float* __restrict__ out)
{
    __shared__ float sT[64][64];
    const int b  = blockIdx.y;
    const int n0 = blockIdx.x * 64;
    const int t  = threadIdx.x;

    for (int idx = t; idx < 64 * 64; idx += 256) {
        int c = idx >> 6, j = idx & 63;
        sT[c][j] = g_o[(((b << 6) + c) << 12) + n0 + j];
    }
    __syncthreads();

    const float g = gamma[0];
    for (int r = 0; r < 16; r++) {
        int outIdx = t + (r << 8);
        int o = outIdx >> 6, j = outIdx & 63;
        const float* wrow = w_out + o * 64;
        float acc = b_out[o];
        #pragma unroll
        for (int c = 0; c < 64; c++) acc += wrow[c] * sT[c][j];
        size_t gi = (size_t)(((b << 6) + o) << 12) + n0 + j;
        out[gi] = g * acc + x[gi];
    }
}

// ---------------- launch ----------------
extern "C" void kernel_launch(void* const* d_in, const int* in_sizes, int n_in,
                              void* d_out, int out_size)
{
    const float* x     = (const float*)d_in[0];
    const float* skip  = (const float*)d_in[1];
    const float* w_qkv = (const float*)d_in[2];
    const float* w_out = (const float*)d_in[3];
    const float* b_out = (const float*)d_in[4];
    const float* gamma = (const float*)d_in[5];
    float* out = (float*)d_out;

    zero_o_kernel<<<1024, 256>>>();
    qkv_kernel<<<dim3(64, BATCH), 256>>>(x, skip, w_qkv);
    scores_kernel<<<dim3(32, 64, BATCH), 256>>>();
    select_softmax_kernel<<<BATCH * NTOK, 256>>>();
    av_kernel<<<dim3(32, 8, BATCH), 256>>>();
    proj_kernel<<<dim3(64, BATCH), 256>>>(x, w_out, b_out, gamma, out);
}